// round 9
// baseline (speedup 1.0000x reference)
#include <cuda_runtime.h>
#include <cstdint>

typedef unsigned long long ull;

#define BN_TOTAL 16384   // B*N
#define NN 2048
#define XSTRIDE 20       // floats per smem row; LDS.128 conflict-free
#define TILEF (64 * XSTRIDE)

__device__ __align__(16) float g_eip[BN_TOTAL];
__device__ __align__(16) float g_ein[BN_TOTAL];
__device__ __align__(16) float g_ejp[BN_TOTAL];
__device__ __align__(16) float g_ejn[BN_TOTAL];

__device__ __forceinline__ void fma2(ull& acc, ull x, ull w) {
    asm("fma.rn.f32x2 %0, %1, %2, %0;" : "+l"(acc) : "l"(x), "l"(w));
}
__device__ __forceinline__ ull pack2(float v) {
    ull r; unsigned u = __float_as_uint(v);
    asm("mov.b64 %0, {%1, %1};" : "=l"(r) : "r"(u));
    return r;
}
__device__ __forceinline__ void cp16(uint32_t dst, const void* src) {
    asm volatile("cp.async.cg.shared.global [%0], [%1], 16;" :: "r"(dst), "l"(src));
}

// epilogue: accumulators (4 ull = 8 conv outputs) -> si/sj contributions
__device__ __forceinline__ void epi(const ull* acc, int to,
                                    const float* bS, const float* b2_,
                                    const float* sFC, float& si, float& sj) {
    float yS[4], y2[4];
    yS[0] = __uint_as_float((unsigned)acc[0]); yS[1] = __uint_as_float((unsigned)(acc[0] >> 32));
    yS[2] = __uint_as_float((unsigned)acc[1]); yS[3] = __uint_as_float((unsigned)(acc[1] >> 32));
    y2[0] = __uint_as_float((unsigned)acc[2]); y2[1] = __uint_as_float((unsigned)(acc[2] >> 32));
    y2[2] = __uint_as_float((unsigned)acc[3]); y2[3] = __uint_as_float((unsigned)(acc[3] >> 32));
    #pragma unroll
    for (int co = 0; co < 4; co++) {
        float sg = 1.0f / (1.0f + __expf(-(y2[co] + b2_[co])));
        float tv = fmaxf(yS[co] + bS[co] + sg, 0.0f);
        si = fmaf(tv, sFC[to * 4 + co], si);
        sj = fmaf(tv, sFC[248 + to * 4 + co], sj);
    }
}

// ---------------------------------------------------------------------------
// k1: fused TimeBlock + dot -> exp factors per (b,n).
// relu(c1+b1+sig(c2+b2)+c3+b3) = relu(conv(w1+w3)+(b1+b3)+sig(conv(w2)+b2)).
// Each warp processes TWO bn tiles jointly so every weight LDS.128 is used
// for both tiles (weight crossbar traffic halved). Warps fully decoupled.
// ---------------------------------------------------------------------------
__global__ void __launch_bounds__(256) score_kernel(
    const float* __restrict__ X,
    const float* __restrict__ cw1, const float* __restrict__ cw2,
    const float* __restrict__ cw3,
    const float* __restrict__ cb1, const float* __restrict__ cb2,
    const float* __restrict__ cb3,
    const float* __restrict__ fcw, const float* __restrict__ fcbp)
{
    __shared__ __align__(16) float sX[8 * 2 * TILEF];    // 80 KB
    __shared__ __align__(16) float sW[384];               // [2][k*16+ci][co]
    __shared__ float sFC[496];

    int tid = threadIdx.x;
    for (int i = tid; i < 384; i += 256) {
        int c   = i / 192;
        int r   = i % 192;
        int pos = r >> 2, co = r & 3;
        int k   = pos >> 4, ci = pos & 15;
        int src = co * 48 + ci * 3 + k;
        sW[i] = (c == 0) ? (cw1[src] + cw3[src]) : cw2[src];
    }
    for (int i = tid; i < 496; i += 256) sFC[i] = fcw[i];
    __syncthreads();   // weights ready; warps independent from here

    int warp = tid >> 5, lane = tid & 31;
    int bn0 = blockIdx.x * 16 + warp * 2;     // this warp: bn0, bn0+1

    float* buf0 = sX + warp * 2 * TILEF;
    float* buf1 = buf0 + TILEF;
    uint32_t b0s = (uint32_t)__cvta_generic_to_shared(buf0);
    uint32_t b1s = (uint32_t)__cvta_generic_to_shared(buf1);

    // async load both tiles
    #pragma unroll
    for (int q = 0; q < 8; q++) {
        int f = q * 32 + lane;
        int row = f >> 2, c4 = (f & 3) * 4;
        uint32_t off = (row * XSTRIDE + c4) * 4;
        cp16(b0s + off, X + (size_t)bn0 * 1024 + f * 4);
        cp16(b1s + off, X + (size_t)(bn0 + 1) * 1024 + f * 4);
    }
    asm volatile("cp.async.commit_group;");
    asm volatile("cp.async.wait_group 0;");
    __syncwarp();

    int to  = lane;
    int to2 = lane + 32;

    ull T[4] = {0,0,0,0};   // tile0, to
    ull U[4] = {0,0,0,0};   // tile0, to2
    ull V[4] = {0,0,0,0};   // tile1, to
    ull Wk[4] = {0,0,0,0};  // tile1, to2

    #pragma unroll
    for (int k = 0; k < 3; k++) {
        const float4* pa = (const float4*)(buf0 + (to + k) * XSTRIDE);
        const float4* pb = (const float4*)(buf0 + (to + 32 + k) * XSTRIDE);
        const float4* pc = (const float4*)(buf1 + (to + k) * XSTRIDE);
        const float4* pd = (const float4*)(buf1 + (to + 32 + k) * XSTRIDE);
        #pragma unroll
        for (int c4 = 0; c4 < 4; c4++) {
            float4 xa = pa[c4], xb = pb[c4], xc = pc[c4], xd = pd[c4];
            const float* fa = (const float*)&xa;
            const float* fb = (const float*)&xb;
            const float* fc = (const float*)&xc;
            const float* fd = (const float*)&xd;
            #pragma unroll
            for (int e = 0; e < 4; e++) {
                int ci = c4 * 4 + e;
                int widx = (k * 16 + ci) * 4;
                ulonglong2 wS = *(const ulonglong2*)(sW + widx);
                ulonglong2 w2 = *(const ulonglong2*)(sW + 192 + widx);
                ull qa = pack2(fa[e]);
                ull qb = pack2(fb[e]);
                ull qc = pack2(fc[e]);
                ull qd = pack2(fd[e]);
                fma2(T[0], qa, wS.x);  fma2(T[1], qa, wS.y);
                fma2(T[2], qa, w2.x);  fma2(T[3], qa, w2.y);
                fma2(U[0], qb, wS.x);  fma2(U[1], qb, wS.y);
                fma2(U[2], qb, w2.x);  fma2(U[3], qb, w2.y);
                fma2(V[0], qc, wS.x);  fma2(V[1], qc, wS.y);
                fma2(V[2], qc, w2.x);  fma2(V[3], qc, w2.y);
                fma2(Wk[0], qd, wS.x); fma2(Wk[1], qd, wS.y);
                fma2(Wk[2], qd, w2.x); fma2(Wk[3], qd, w2.y);
            }
        }
    }

    float bS[4], b2_[4];
    #pragma unroll
    for (int co = 0; co < 4; co++) { bS[co] = cb1[co] + cb3[co]; b2_[co] = cb2[co]; }
    float fcb = fcbp[0];

    // tile 0
    {
        float si = 0.f, sj = 0.f;
        epi(T, to, bS, b2_, sFC, si, sj);
        if (to2 < 62) epi(U, to2, bS, b2_, sFC, si, sj);
        #pragma unroll
        for (int off = 16; off > 0; off >>= 1) {
            si += __shfl_xor_sync(0xffffffffu, si, off);
            sj += __shfl_xor_sync(0xffffffffu, sj, off);
        }
        if (lane == 0) {
            float sif = si + fcb;
            g_eip[bn0] = __expf(sif);
            g_ein[bn0] = __expf(0.01f * sif);
            g_ejp[bn0] = __expf(sj);
            g_ejn[bn0] = __expf(0.01f * sj);
        }
    }
    // tile 1
    {
        float si = 0.f, sj = 0.f;
        epi(V, to, bS, b2_, sFC, si, sj);
        if (to2 < 62) epi(Wk, to2, bS, b2_, sFC, si, sj);
        #pragma unroll
        for (int off = 16; off > 0; off >>= 1) {
            si += __shfl_xor_sync(0xffffffffu, si, off);
            sj += __shfl_xor_sync(0xffffffffu, sj, off);
        }
        if (lane == 0) {
            int bn = bn0 + 1;
            float sif = si + fcb;
            g_eip[bn] = __expf(sif);
            g_ein[bn] = __expf(0.01f * sif);
            g_ejp[bn] = __expf(sj);
            g_ejn[bn] = __expf(0.01f * sj);
        }
    }
}

// ---------------------------------------------------------------------------
// k2: masked softmax, pure-FMA form (A in {0,1} used as numbers):
//   denom = 2048 + sum_j a_j*(e_j - 1);  out_j = e_j * a_j / denom.
// One block = 8 rows of one batch (2048 blocks): P/Q register cache shared
// by 8 rows. launch_bounds(256,4) caps regs at 64 -> 4 CTAs/SM.
// Eip/Ein and A reloaded in the write phase (L1-hot).
// ---------------------------------------------------------------------------
__global__ void __launch_bounds__(256, 4) softmax_kernel(
    const float* __restrict__ A, float* __restrict__ out)
{
    int tile = blockIdx.x;          // 2048 = 8 batches x 256 row-tiles
    int it   = tile & 255;
    int b    = tile >> 8;
    int i0   = it * 8;
    int t    = threadIdx.x;
    int j0   = t * 4;

    float4 P0 = *(const float4*)(g_ejp + b * NN + j0);
    float4 P1 = *(const float4*)(g_ejp + b * NN + j0 + 1024);
    float4 Q0 = *(const float4*)(g_ejn + b * NN + j0);
    float4 Q1 = *(const float4*)(g_ejn + b * NN + j0 + 1024);

    float acc[8];

    #pragma unroll
    for (int ii = 0; ii < 8; ii++) {
        int i = i0 + ii;
        float4 a0 = __ldg((const float4*)(A + (size_t)i * NN + j0));
        float4 a1 = __ldg((const float4*)(A + (size_t)i * NN + j0 + 1024));
        float Ep = __ldg(g_eip + b * NN + i);
        float En = __ldg(g_ein + b * NN + i);
        float s = 0.f;
        s = fmaf(fmaxf(Ep * P0.x, En * Q0.x) - 1.f, a0.x, s);
        s = fmaf(fmaxf(Ep * P0.y, En * Q0.y) - 1.f, a0.y, s);
        s = fmaf(fmaxf(Ep * P0.z, En * Q0.z) - 1.f, a0.z, s);
        s = fmaf(fmaxf(Ep * P0.w, En * Q0.w) - 1.f, a0.w, s);
        s = fmaf(fmaxf(Ep * P1.x, En * Q1.x) - 1.f, a1.x, s);
        s = fmaf(fmaxf(Ep * P1.y, En * Q1.y) - 1.f, a1.y, s);
        s = fmaf(fmaxf(Ep * P1.z, En * Q1.z) - 1.f, a1.z, s);
        s = fmaf(fmaxf(Ep * P1.w, En * Q1.w) - 1.f, a1.w, s);
        acc[ii] = s;
    }

    #pragma unroll
    for (int off = 16; off > 0; off >>= 1) {
        #pragma unroll
        for (int ii = 0; ii < 8; ii++)
            acc[ii] += __shfl_xor_sync(0xffffffffu, acc[ii], off);
    }

    __shared__ float red[8][8];
    __shared__ float s_r[8];
    if ((t & 31) == 0) {
        int w = t >> 5;
        #pragma unroll
        for (int ii = 0; ii < 8; ii++) red[ii][w] = acc[ii];
    }
    __syncthreads();
    if (t < 8) {
        float s = 2048.f + red[t][0] + red[t][1] + red[t][2] + red[t][3]
                         + red[t][4] + red[t][5] + red[t][6] + red[t][7];
        s_r[t] = 1.0f / s;
    }
    __syncthreads();

    #pragma unroll
    for (int ii = 0; ii < 8; ii++) {
        int i = i0 + ii;
        float r = s_r[ii];
        float Ep = __ldg(g_eip + b * NN + i);   // L1 hit
        float En = __ldg(g_ein + b * NN + i);
        float4 a0 = __ldg((const float4*)(A + (size_t)i * NN + j0));
        float4 a1 = __ldg((const float4*)(A + (size_t)i * NN + j0 + 1024));
        float* O = out + ((size_t)(b * NN + i)) * NN;
        float4 o0, o1;
        o0.x = fmaxf(Ep * P0.x, En * Q0.x) * a0.x * r;
        o0.y = fmaxf(Ep * P0.y, En * Q0.y) * a0.y * r;
        o0.z = fmaxf(Ep * P0.z, En * Q0.z) * a0.z * r;
        o0.w = fmaxf(Ep * P0.w, En * Q0.w) * a0.w * r;
        o1.x = fmaxf(Ep * P1.x, En * Q1.x) * a1.x * r;
        o1.y = fmaxf(Ep * P1.y, En * Q1.y) * a1.y * r;
        o1.z = fmaxf(Ep * P1.z, En * Q1.z) * a1.z * r;
        o1.w = fmaxf(Ep * P1.w, En * Q1.w) * a1.w * r;
        __stcs((float4*)(O + j0), o0);
        __stcs((float4*)(O + j0 + 1024), o1);
    }
}

// ---------------------------------------------------------------------------
extern "C" void kernel_launch(void* const* d_in, const int* in_sizes, int n_in,
                              void* d_out, int out_size) {
    const float* X   = (const float*)d_in[0];
    const float* A   = (const float*)d_in[1];
    const float* cw1 = (const float*)d_in[2];
    const float* cb1 = (const float*)d_in[3];
    const float* cw2 = (const float*)d_in[4];
    const float* cb2 = (const float*)d_in[5];
    const float* cw3 = (const float*)d_in[6];
    const float* cb3 = (const float*)d_in[7];
    const float* fcw = (const float*)d_in[8];
    const float* fcb = (const float*)d_in[9];
    float* out = (float*)d_out;

    score_kernel<<<BN_TOTAL / 16, 256>>>(X, cw1, cw2, cw3, cb1, cb2, cb3, fcw, fcb);
    softmax_kernel<<<2048, 256>>>(A, out);
}